// round 15
// baseline (speedup 1.0000x reference)
#include <cuda_runtime.h>
#include <cstddef>

// Shapes (fixed per reference): B=16, Cin=Cout=256, S=512, H=W=64, K=3
#define BATCH 16
#define CINC  256
#define COUTC 256
#define SDIM  512
#define HH    64
#define WW    64

// Conv tiling
#define CK     8      // cin per chunk
#define COUT_T 32     // couts per block
#define H_T    4      // output rows per block
#define XH     6      // H_T + 2 (halo)
#define XW     66     // WW + 2 (halo)

// Scratch (static device globals — no allocation allowed)
__device__ float g_style[BATCH * CINC];   // style[b][cin]
__device__ float g_wsq[COUTC * CINC];     // sum_kk w^2 per (cout,cin)
__device__ float g_demod[BATCH * COUTC];  // 1/sqrt(sum + eps)

// ---------------------------------------------------------------------------
// Kernel 1: style[b][c] = y[b] . style_w[c] + style_b[c]   (one warp per (b,c))
// ---------------------------------------------------------------------------
__global__ void style_kernel(const float* __restrict__ y,
                             const float* __restrict__ sw,
                             const float* __restrict__ sb) {
    int gwarp = (blockIdx.x * blockDim.x + threadIdx.x) >> 5;
    int lane  = threadIdx.x & 31;
    if (gwarp >= BATCH * CINC) return;
    int b = gwarp >> 8;
    int c = gwarp & 255;
    const float* yr = y + (size_t)b * SDIM;
    const float* wr = sw + (size_t)c * SDIM;
    float s = 0.f;
    #pragma unroll 4
    for (int i = lane; i < SDIM; i += 32) s += yr[i] * wr[i];
    #pragma unroll
    for (int o = 16; o; o >>= 1) s += __shfl_xor_sync(0xffffffffu, s, o);
    if (lane == 0) g_style[gwarp] = s + sb[c];
}

// ---------------------------------------------------------------------------
// Kernel 2: wsq[co][ci] = sum_kk w[co][ci][kk]^2
// ---------------------------------------------------------------------------
__global__ void wsq_kernel(const float* __restrict__ w) {
    int i = blockIdx.x * blockDim.x + threadIdx.x;
    if (i >= COUTC * CINC) return;
    const float* p = w + (size_t)i * 9;
    float s = 0.f;
    #pragma unroll
    for (int k = 0; k < 9; ++k) s += p[k] * p[k];
    g_wsq[i] = s;
}

// ---------------------------------------------------------------------------
// Kernel 3: demod[b][co] = rsqrt( sum_ci style[b][ci]^2 * wsq[co][ci] + eps )
// (one warp per (b,co))
// ---------------------------------------------------------------------------
__global__ void demod_kernel() {
    int gwarp = (blockIdx.x * blockDim.x + threadIdx.x) >> 5;
    int lane  = threadIdx.x & 31;
    if (gwarp >= BATCH * COUTC) return;
    int b  = gwarp >> 8;
    int co = gwarp & 255;
    float s = 0.f;
    #pragma unroll 2
    for (int c = lane; c < CINC; c += 32) {
        float st = g_style[b * CINC + c];
        s += st * st * g_wsq[co * CINC + c];
    }
    #pragma unroll
    for (int o = 16; o; o >>= 1) s += __shfl_xor_sync(0xffffffffu, s, o);
    if (lane == 0) g_demod[gwarp] = rsqrtf(s + 1e-8f);
}

// ---------------------------------------------------------------------------
// Kernel 4: the conv.
//   Block = 256 threads (8 warps). Tile: COUT_T=32 couts x H_T=4 rows x 64 cols.
//   Each warp owns 4 couts; each thread owns 4 couts x 4 rows x 2 cols = 32 accs.
//   Loop cin in chunks of CK=8:
//     SMEM x tile: [CK][6][66] (halo, zero-padded, pre-scaled by style[b][cin])
//     SMEM w tile: [COUT_T][CK][9]
//   Epilogue: *demod[b][co] + bias[co].
// ---------------------------------------------------------------------------
__global__ __launch_bounds__(256, 2)
void conv_kernel(const float* __restrict__ x,
                 const float* __restrict__ wgt,
                 const float* __restrict__ bias,
                 float* __restrict__ out) {
    __shared__ float sx[CK][XH][XW];        // 3168 floats
    __shared__ float swt[COUT_T][CK][9];    // 2304 floats
    __shared__ float ssty[CINC];            // 256 floats

    const int tid  = threadIdx.x;
    const int lane = tid & 31;
    const int warp = tid >> 5;
    const int h0   = blockIdx.x * H_T;
    const int co0  = blockIdx.y * COUT_T;
    const int b    = blockIdx.z;

    // preload all styles for this batch sample (1 KB)
    ssty[tid] = g_style[b * CINC + tid];
    __syncthreads();

    float acc[4][4][2];
    #pragma unroll
    for (int a = 0; a < 4; ++a)
        #pragma unroll
        for (int h = 0; h < 4; ++h) { acc[a][h][0] = 0.f; acc[a][h][1] = 0.f; }

    const size_t x_b = (size_t)b * CINC * HH * WW;

    for (int ci0 = 0; ci0 < CINC; ci0 += CK) {
        // ---- stage x tile (style-scaled, zero halo) ----
        #pragma unroll
        for (int i = tid; i < CK * XH * XW; i += 256) {
            int cin = i / (XH * XW);
            int rem = i - cin * (XH * XW);
            int r   = rem / XW;
            int c   = rem - r * XW;
            int gh  = h0 + r - 1;
            int gw  = c - 1;
            float v = 0.f;
            if ((unsigned)gh < (unsigned)HH && (unsigned)gw < (unsigned)WW)
                v = x[x_b + ((size_t)(ci0 + cin) * HH + gh) * WW + gw] * ssty[ci0 + cin];
            sx[cin][r][c] = v;
        }
        // ---- stage weight tile ----
        #pragma unroll
        for (int i = tid; i < COUT_T * CK * 9; i += 256) {
            int co  = i / (CK * 9);
            int rem = i - co * (CK * 9);
            int cin = rem / 9;
            int kk  = rem - cin * 9;
            swt[co][cin][kk] = wgt[((size_t)(co0 + co) * CINC + ci0 + cin) * 9 + kk];
        }
        __syncthreads();

        // ---- compute ----
        for (int cin = 0; cin < CK; ++cin) {
            #pragma unroll
            for (int ky = 0; ky < 3; ++ky) {
                float a0[4][3], a1[4][3];
                #pragma unroll
                for (int h = 0; h < 4; ++h) {
                    #pragma unroll
                    for (int c = 0; c < 3; ++c) {
                        a0[h][c] = sx[cin][h + ky][lane + c];
                        a1[h][c] = sx[cin][h + ky][lane + 32 + c];
                    }
                }
                #pragma unroll
                for (int kx = 0; kx < 3; ++kx) {
                    float w0 = swt[warp * 4 + 0][cin][ky * 3 + kx];
                    float w1 = swt[warp * 4 + 1][cin][ky * 3 + kx];
                    float w2 = swt[warp * 4 + 2][cin][ky * 3 + kx];
                    float w3 = swt[warp * 4 + 3][cin][ky * 3 + kx];
                    #pragma unroll
                    for (int h = 0; h < 4; ++h) {
                        float v0 = a0[h][kx];
                        float v1 = a1[h][kx];
                        acc[0][h][0] += v0 * w0; acc[0][h][1] += v1 * w0;
                        acc[1][h][0] += v0 * w1; acc[1][h][1] += v1 * w1;
                        acc[2][h][0] += v0 * w2; acc[2][h][1] += v1 * w2;
                        acc[3][h][0] += v0 * w3; acc[3][h][1] += v1 * w3;
                    }
                }
            }
        }
        __syncthreads();
    }

    // ---- epilogue: demod scale + bias, store ----
    #pragma unroll
    for (int a = 0; a < 4; ++a) {
        int cog  = co0 + warp * 4 + a;
        float dm = g_demod[b * COUTC + cog];
        float bv = bias[cog];
        #pragma unroll
        for (int h = 0; h < 4; ++h) {
            size_t base = (((size_t)b * COUTC + cog) * HH + h0 + h) * WW;
            out[base + lane]      = acc[a][h][0] * dm + bv;
            out[base + lane + 32] = acc[a][h][1] * dm + bv;
        }
    }
}

// ---------------------------------------------------------------------------
// Launch: inputs in metadata order:
//   d_in[0]=x [16,256,64,64] f32, d_in[1]=y [16,512] f32,
//   d_in[2]=weights [256,256,3,3] f32, d_in[3]=bias [256] f32,
//   d_in[4]=style_w [256,512] f32, d_in[5]=style_b [256] f32
// out: [16,256,64,64] f32
// ---------------------------------------------------------------------------
extern "C" void kernel_launch(void* const* d_in, const int* in_sizes, int n_in,
                              void* d_out, int out_size) {
    const float* x       = (const float*)d_in[0];
    const float* y       = (const float*)d_in[1];
    const float* weights = (const float*)d_in[2];
    const float* bias    = (const float*)d_in[3];
    const float* style_w = (const float*)d_in[4];
    const float* style_b = (const float*)d_in[5];
    float* out = (float*)d_out;

    // 1) style: 16*256 warps, 8 warps/block -> 512 blocks
    style_kernel<<<512, 256>>>(y, style_w, style_b);
    // 2) per-(cout,cin) weight sum-of-squares
    wsq_kernel<<<(COUTC * CINC + 255) / 256, 256>>>(weights);
    // 3) demod factors: 16*256 warps -> 512 blocks
    demod_kernel<<<512, 256>>>();
    // 4) conv: grid (h tiles, cout tiles, batch) = (16, 8, 16)
    dim3 grid(HH / H_T, COUTC / COUT_T, BATCH);
    conv_kernel<<<grid, 256>>>(x, weights, bias, out);
}